// round 7
// baseline (speedup 1.0000x reference)
#include <cuda_runtime.h>
#include <math.h>

// N=500000, D=64, A=200000, temperature=1, cross_weight=1
#define MAX_NCE_BLOCKS 16384
#define WPB 8                    // warps per block (256 threads)

__device__ float g_partials[MAX_NCE_BLOCKS];
__device__ unsigned int g_count = 0;

__device__ __forceinline__ float dot4(float4 a, float4 b) {
    return a.x * b.x + a.y * b.y + a.z * b.z + a.w * b.w;
}
__device__ __forceinline__ float4 avg4(float4 a, float4 b) {
    return make_float4(0.5f * (a.x + b.x), 0.5f * (a.y + b.y),
                       0.5f * (a.z + b.z), 0.5f * (a.w + b.w));
}
__device__ __forceinline__ float hsum16(float v) {
#pragma unroll
    for (int o = 8; o > 0; o >>= 1)
        v += __shfl_xor_sync(0xFFFFFFFFu, v, o);
    return v;
}
__device__ __forceinline__ float softplus_stable(float x) {
    return (x > 0.0f) ? (x + log1pf(expf(-x))) : log1pf(expf(x));
}
__device__ __forceinline__ float cos_sim(float dot, float n1sq, float n2sq) {
    float den = sqrtf(n1sq) * sqrtf(n2sq);
    return dot / fmaxf(den, 1e-8f);
}
__device__ __forceinline__ float4 ldcg4(const float* p) {
    return __ldcg((const float4*)p);
}

__global__ __launch_bounds__(256, 6) void mvr_fused_kernel(
    const float* __restrict__ g1, const float* __restrict__ g2,
    const float* __restrict__ s1, const float* __restrict__ s2,
    const float* __restrict__ w,
    const int* __restrict__ aidx, const int* __restrict__ nidx,
    float* __restrict__ out, int N, int A, int scalarOff,
    int nceBlocks, int totalBlocks)
{
    const int tid  = threadIdx.x;
    const int warp = tid >> 5;
    const int lane = tid & 31;
    const int half = lane >> 4;   // which 16-lane group
    const int l16  = lane & 15;   // lane within group (4 floats -> D=64)

    // Bresenham interleave of NCE and streaming blocks across blockIdx space:
    // c(b) = floor(b*nce/T) counts NCE blocks before b.
    const unsigned b = blockIdx.x;
    const unsigned c  = (unsigned)(((unsigned long long)b * (unsigned)nceBlocks) / (unsigned)totalBlocks);
    const unsigned c1 = (unsigned)(((unsigned long long)(b + 1) * (unsigned)nceBlocks) / (unsigned)totalBlocks);
    const bool isNce = (c1 != c);

    if (!isNce) {
        // ---------- Streaming embedding fusion: 16 lanes per row, 2 rows/warp ----------
        int embIdx = (int)(b - c);
        int row = embIdx * (WPB * 2) + warp * 2 + half;
        bool v = row < N;
        unsigned base = v ? ((unsigned)row * 64u + (unsigned)l16 * 4u) : 0u;

        float4 a = __ldcs((const float4*)(g1 + base));
        float4 bb = __ldcs((const float4*)(g2 + base));
        float4 cc = __ldcs((const float4*)(s1 + base));
        float4 d = __ldcs((const float4*)(s2 + base));

        float4 ga = avg4(a, bb);
        float4 sa = avg4(cc, d);

        float4 wg = *(const float4*)(w + l16 * 4);
        float4 ws = *(const float4*)(w + 64 + l16 * 4);

        float part = hsum16(dot4(ga, wg) + dot4(sa, ws));
        float alpha = 1.0f / (1.0f + expf(-part));

        float4 o;
        o.x = fmaf(alpha, ga.x - sa.x, sa.x);
        o.y = fmaf(alpha, ga.y - sa.y, sa.y);
        o.z = fmaf(alpha, ga.z - sa.z, sa.z);
        o.w = fmaf(alpha, ga.w - sa.w, sa.w);
        if (v) __stcs((float4*)(out + base), o);
        return;
    }

    // ---------- InfoNCE: 2 items per warp (16 lanes each), single pass ----------
    __shared__ float sh[WPB];
    __shared__ bool isLast;
    __shared__ float red[256];

    int nceIdx = (int)c;
    float acc = 0.0f;
    const int stride = nceBlocks * (WPB * 2);   // covers A in one pass for this problem
    int item0 = nceIdx * (WPB * 2) + warp * 2 + half;

#pragma unroll 1
    for (int item = item0; item < A + half; item += stride) {
        bool valid = item < A;
        int it = valid ? item : 0;
        int ai = __ldg(aidx + it);
        int ni = __ldg(nidx + it);
        unsigned ba = (unsigned)ai * 64u + (unsigned)l16 * 4u;
        unsigned bn = (unsigned)ni * 64u + (unsigned)l16 * 4u;

        // all 7 row loads issued up front for MLP
        float4 g1a = ldcg4(g1 + ba);
        float4 g2a = ldcg4(g2 + ba);
        float4 g2n = ldcg4(g2 + bn);
        float4 s1a = ldcg4(s1 + ba);
        float4 s2a = ldcg4(s2 + ba);
        float4 s1n = ldcg4(s1 + bn);
        float4 s2n = ldcg4(s2 + bn);

        // graph view: consume g2n early
        float v0 = hsum16(dot4(g1a, g2a));
        float v1 = hsum16(dot4(g1a, g1a));
        float v2 = hsum16(dot4(g2a, g2a));
        float v3 = hsum16(dot4(g1a, g2n));
        float v4 = hsum16(dot4(g2n, g2n));       // g2n dead
        float4 gav = avg4(g1a, g2a);             // g1a,g2a -> gav

        // sequence view: consume s1n into snv immediately
        float4 snv = avg4(s1n, s2n);             // s1n dead
        float v5 = hsum16(dot4(s1a, s2a));
        float v6 = hsum16(dot4(s1a, s1a));
        float v7 = hsum16(dot4(s2a, s2a));
        float v8 = hsum16(dot4(s1a, s2n));
        float v9 = hsum16(dot4(s2n, s2n));       // s2n dead
        float4 sav = avg4(s1a, s2a);             // s1a,s2a -> sav

        // cross view
        float v10 = hsum16(dot4(gav, sav));
        float v11 = hsum16(dot4(gav, gav));
        float v12 = hsum16(dot4(sav, sav));
        float v13 = hsum16(dot4(gav, snv));
        float v14 = hsum16(dot4(snv, snv));

        float loss = softplus_stable(cos_sim(v3,  v1,  v4)  - cos_sim(v0,  v1,  v2))
                   + softplus_stable(cos_sim(v8,  v6,  v9)  - cos_sim(v5,  v6,  v7))
                   + softplus_stable(cos_sim(v13, v11, v14) - cos_sim(v10, v11, v12));
        acc += valid ? loss : 0.0f;
    }

    // combine the two half-warp accumulators
    float tot = acc + __shfl_xor_sync(0xFFFFFFFFu, acc, 16);
    if (lane == 0) sh[warp] = tot;
    __syncthreads();

    if (tid == 0) {
        float s = 0.0f;
#pragma unroll
        for (int i = 0; i < WPB; i++) s += sh[i];
        g_partials[nceIdx] = s;
        __threadfence();
        unsigned t = atomicAdd(&g_count, 1u);
        isLast = (t == (unsigned)nceBlocks - 1u);
    }
    __syncthreads();

    if (isLast) {
        __threadfence();
        float s = 0.0f;
        for (int i = tid; i < nceBlocks; i += 256)
            s += g_partials[i];
        red[tid] = s;
        __syncthreads();
#pragma unroll
        for (int st = 128; st > 0; st >>= 1) {
            if (tid < st) red[tid] += red[tid + st];
            __syncthreads();
        }
        if (tid == 0) {
            out[scalarOff] = red[0] / (float)A;
            g_count = 0;   // reset for next graph replay
        }
    }
}

extern "C" void kernel_launch(void* const* d_in, const int* in_sizes, int n_in,
                              void* d_out, int out_size)
{
    const float* g1 = (const float*)d_in[0];
    const float* g2 = (const float*)d_in[1];
    const float* s1 = (const float*)d_in[2];
    const float* s2 = (const float*)d_in[3];
    const float* w  = (const float*)d_in[4];
    const int* aidx = (const int*)d_in[5];
    const int* nidx = (const int*)d_in[6];
    float* out = (float*)d_out;

    int N = in_sizes[0] / 64;
    int A = in_sizes[5];

    int embBlocks = (N + WPB * 2 - 1) / (WPB * 2);          // 31250
    int nceBlocks = (A + WPB * 2 - 1) / (WPB * 2);          // 12500
    if (nceBlocks > MAX_NCE_BLOCKS) nceBlocks = MAX_NCE_BLOCKS;
    int totalBlocks = embBlocks + nceBlocks;                // 43750

    int scalarOff = N * 64;   // 32,000,000 fits in int

    mvr_fused_kernel<<<totalBlocks, 256>>>(
        g1, g2, s1, s2, w, aidx, nidx, out, N, A, scalarOff,
        nceBlocks, totalBlocks);
}

// round 8
// speedup vs baseline: 1.1109x; 1.1109x over previous
#include <cuda_runtime.h>
#include <math.h>

// N=500000, D=64, A=200000, temperature=1, cross_weight=1
#define NCE_BLOCKS 2048
#define WPB 8                    // warps per block (256 threads)
#define ROWS_PER_BLOCK 32        // streaming: 4 rows/warp, 2 row-pairs

__device__ float g_partials[NCE_BLOCKS];
__device__ unsigned int g_count = 0;

__device__ __forceinline__ float dot4(float4 a, float4 b) {
    return a.x * b.x + a.y * b.y + a.z * b.z + a.w * b.w;
}
__device__ __forceinline__ float4 avg4(float4 a, float4 b) {
    return make_float4(0.5f * (a.x + b.x), 0.5f * (a.y + b.y),
                       0.5f * (a.z + b.z), 0.5f * (a.w + b.w));
}
__device__ __forceinline__ float hsum16(float v) {
#pragma unroll
    for (int o = 8; o > 0; o >>= 1)
        v += __shfl_xor_sync(0xFFFFFFFFu, v, o);
    return v;
}
// two independent 16-lane reductions interleaved (hides shuffle latency)
__device__ __forceinline__ void hsum16x2(float& a, float& b) {
#pragma unroll
    for (int o = 8; o > 0; o >>= 1) {
        float ta = __shfl_xor_sync(0xFFFFFFFFu, a, o);
        float tb = __shfl_xor_sync(0xFFFFFFFFu, b, o);
        a += ta;
        b += tb;
    }
}
__device__ __forceinline__ float softplus_stable(float x) {
    return (x > 0.0f) ? (x + log1pf(expf(-x))) : log1pf(expf(x));
}
__device__ __forceinline__ float cos_sim(float dot, float n1sq, float n2sq) {
    float den = sqrtf(n1sq) * sqrtf(n2sq);
    return dot / fmaxf(den, 1e-8f);
}
__device__ __forceinline__ float4 ldcg4(const float* p) {
    return __ldcg((const float4*)p);
}

__global__ __launch_bounds__(256, 6) void mvr_fused_kernel(
    const float* __restrict__ g1, const float* __restrict__ g2,
    const float* __restrict__ s1, const float* __restrict__ s2,
    const float* __restrict__ w,
    const int* __restrict__ aidx, const int* __restrict__ nidx,
    float* __restrict__ out, int N, int A, int scalarOff)
{
    const int tid  = threadIdx.x;
    const int warp = tid >> 5;
    const int lane = tid & 31;
    const int half = lane >> 4;   // which 16-lane group
    const int l16  = lane & 15;   // lane within group (4 floats -> D=64)

    if ((int)blockIdx.x >= NCE_BLOCKS) {
        // ---------- Streaming embedding fusion: 4 rows/warp (2 row-pairs) ----------
        int row0 = ((int)blockIdx.x - NCE_BLOCKS) * ROWS_PER_BLOCK + warp * 2 + half;
        int row1 = row0 + 16;
        bool v0r = row0 < N;
        bool v1r = row1 < N;
        unsigned base0 = v0r ? ((unsigned)row0 * 64u + (unsigned)l16 * 4u) : 0u;
        unsigned base1 = v1r ? ((unsigned)row1 * 64u + (unsigned)l16 * 4u) : 0u;

        // 8 loads in flight
        float4 a0 = __ldcs((const float4*)(g1 + base0));
        float4 b0 = __ldcs((const float4*)(g2 + base0));
        float4 c0 = __ldcs((const float4*)(s1 + base0));
        float4 d0 = __ldcs((const float4*)(s2 + base0));
        float4 a1 = __ldcs((const float4*)(g1 + base1));
        float4 b1 = __ldcs((const float4*)(g2 + base1));
        float4 c1 = __ldcs((const float4*)(s1 + base1));
        float4 d1 = __ldcs((const float4*)(s2 + base1));

        float4 wg = *(const float4*)(w + l16 * 4);
        float4 ws = *(const float4*)(w + 64 + l16 * 4);

        float4 ga0 = avg4(a0, b0);
        float4 sa0 = avg4(c0, d0);
        float4 ga1 = avg4(a1, b1);
        float4 sa1 = avg4(c1, d1);

        float p0 = dot4(ga0, wg) + dot4(sa0, ws);
        float p1 = dot4(ga1, wg) + dot4(sa1, ws);
        hsum16x2(p0, p1);   // interleaved chains

        float al0 = 1.0f / (1.0f + expf(-p0));
        float al1 = 1.0f / (1.0f + expf(-p1));

        float4 o0, o1;
        o0.x = fmaf(al0, ga0.x - sa0.x, sa0.x);
        o0.y = fmaf(al0, ga0.y - sa0.y, sa0.y);
        o0.z = fmaf(al0, ga0.z - sa0.z, sa0.z);
        o0.w = fmaf(al0, ga0.w - sa0.w, sa0.w);
        o1.x = fmaf(al1, ga1.x - sa1.x, sa1.x);
        o1.y = fmaf(al1, ga1.y - sa1.y, sa1.y);
        o1.z = fmaf(al1, ga1.z - sa1.z, sa1.z);
        o1.w = fmaf(al1, ga1.w - sa1.w, sa1.w);
        if (v0r) __stcs((float4*)(out + base0), o0);
        if (v1r) __stcs((float4*)(out + base1), o1);
        return;
    }

    // ---------- InfoNCE: 2 items per warp (16 lanes each), grid-stride ----------
    __shared__ float sh[WPB];
    __shared__ bool isLast;
    __shared__ float red[256];

    float acc = 0.0f;
    const int stride = NCE_BLOCKS * WPB * 2;
    int item0 = (int)blockIdx.x * (WPB * 2) + warp * 2 + half;

#pragma unroll 1
    for (int item = item0; item < A + half; item += stride) {
        bool valid = item < A;
        int it = valid ? item : 0;
        int ai = __ldg(aidx + it);
        int ni = __ldg(nidx + it);
        unsigned ba = (unsigned)ai * 64u + (unsigned)l16 * 4u;
        unsigned bn = (unsigned)ni * 64u + (unsigned)l16 * 4u;

        // all 7 row loads issued up front for MLP
        float4 g1a = ldcg4(g1 + ba);
        float4 g2a = ldcg4(g2 + ba);
        float4 g2n = ldcg4(g2 + bn);
        float4 s1a = ldcg4(s1 + ba);
        float4 s2a = ldcg4(s2 + ba);
        float4 s1n = ldcg4(s1 + bn);
        float4 s2n = ldcg4(s2 + bn);

        // graph view: consume g2n early
        float v0 = hsum16(dot4(g1a, g2a));
        float v1 = hsum16(dot4(g1a, g1a));
        float v2 = hsum16(dot4(g2a, g2a));
        float v3 = hsum16(dot4(g1a, g2n));
        float v4 = hsum16(dot4(g2n, g2n));       // g2n dead
        float4 gav = avg4(g1a, g2a);             // g1a,g2a -> gav

        // sequence view: consume s1n into snv immediately
        float4 snv = avg4(s1n, s2n);             // s1n dead
        float v5 = hsum16(dot4(s1a, s2a));
        float v6 = hsum16(dot4(s1a, s1a));
        float v7 = hsum16(dot4(s2a, s2a));
        float v8 = hsum16(dot4(s1a, s2n));
        float v9 = hsum16(dot4(s2n, s2n));       // s2n dead
        float4 sav = avg4(s1a, s2a);             // s1a,s2a -> sav

        // cross view
        float v10 = hsum16(dot4(gav, sav));
        float v11 = hsum16(dot4(gav, gav));
        float v12 = hsum16(dot4(sav, sav));
        float v13 = hsum16(dot4(gav, snv));
        float v14 = hsum16(dot4(snv, snv));

        float loss = softplus_stable(cos_sim(v3,  v1,  v4)  - cos_sim(v0,  v1,  v2))
                   + softplus_stable(cos_sim(v8,  v6,  v9)  - cos_sim(v5,  v6,  v7))
                   + softplus_stable(cos_sim(v13, v11, v14) - cos_sim(v10, v11, v12));
        acc += valid ? loss : 0.0f;
    }

    // combine the two half-warp accumulators
    float tot = acc + __shfl_xor_sync(0xFFFFFFFFu, acc, 16);
    if (lane == 0) sh[warp] = tot;
    __syncthreads();

    if (tid == 0) {
        float s = 0.0f;
#pragma unroll
        for (int i = 0; i < WPB; i++) s += sh[i];
        g_partials[blockIdx.x] = s;
        __threadfence();
        unsigned t = atomicAdd(&g_count, 1u);
        isLast = (t == NCE_BLOCKS - 1);
    }
    __syncthreads();

    if (isLast) {
        __threadfence();
        float s = 0.0f;
        for (int i = tid; i < NCE_BLOCKS; i += 256)
            s += g_partials[i];
        red[tid] = s;
        __syncthreads();
#pragma unroll
        for (int st = 128; st > 0; st >>= 1) {
            if (tid < st) red[tid] += red[tid + st];
            __syncthreads();
        }
        if (tid == 0) {
            out[scalarOff] = red[0] / (float)A;
            g_count = 0;   // reset for next graph replay
        }
    }
}

extern "C" void kernel_launch(void* const* d_in, const int* in_sizes, int n_in,
                              void* d_out, int out_size)
{
    const float* g1 = (const float*)d_in[0];
    const float* g2 = (const float*)d_in[1];
    const float* s1 = (const float*)d_in[2];
    const float* s2 = (const float*)d_in[3];
    const float* w  = (const float*)d_in[4];
    const int* aidx = (const int*)d_in[5];
    const int* nidx = (const int*)d_in[6];
    float* out = (float*)d_out;

    int N = in_sizes[0] / 64;
    int A = in_sizes[5];

    int embBlocks = (N + ROWS_PER_BLOCK - 1) / ROWS_PER_BLOCK;  // 15625
    int scalarOff = N * 64;   // 32,000,000 fits in int

    mvr_fused_kernel<<<NCE_BLOCKS + embBlocks, 256>>>(
        g1, g2, s1, s2, w, aidx, nidx, out, N, A, scalarOff);
}